// round 15
// baseline (speedup 1.0000x reference)
#include <cuda_runtime.h>
#include <cuda_bf16.h>
#include <cuda_fp16.h>
#include <cstdint>
#include <math.h>

typedef unsigned long long ull;
typedef unsigned int u32;

#define NNODES 50000
#define NEDGES 500000
#define ETOT   (NEDGES + NNODES)
#define INF    128
#define HID    64
#define HEADS  4
#define ZW     (HEADS * HID)       // 256
#define NG     16
#define OUTF   326000
#define NPAD   50048               // multiple of 128
#define NZBLK  (NPAD / 64)         // 782 z tiles
#define NBLK   196                 // ceil(NNODES/256)

#define LDSM4(r0,r1,r2,r3,addr) \
    asm volatile("ldmatrix.sync.aligned.m8n8.x4.shared.b16 {%0,%1,%2,%3}, [%4];" \
        : "=r"(r0),"=r"(r1),"=r"(r2),"=r"(r3) : "r"(addr))
#define LDSM4T(r0,r1,r2,r3,addr) \
    asm volatile("ldmatrix.sync.aligned.m8n8.x4.trans.shared.b16 {%0,%1,%2,%3}, [%4];" \
        : "=r"(r0),"=r"(r1),"=r"(r2),"=r"(r3) : "r"(addr))
#define MMA16816(d,a0,a1,a2,a3,b0,b1) \
    asm volatile("mma.sync.aligned.m16n8k16.row.col.f32.f16.f16.f32 " \
        "{%0,%1,%2,%3},{%4,%5,%6,%7},{%8,%9},{%0,%1,%2,%3};" \
        : "+f"(d[0]),"+f"(d[1]),"+f"(d[2]),"+f"(d[3]) \
        : "r"(a0),"r"(a1),"r"(a2),"r"(a3),"r"(b0),"r"(b1))

// ---------------- scratch ----------------------------------------------------
__device__ float  g_h[(size_t)NPAD * HID];                 // fp32 h (pool input)
__device__ __align__(16) __half g_hh[(size_t)NPAD * HID];  // fp16 h (GEMM input)
__device__ __align__(16) __half g_xh[(size_t)NPAD * INF];  // fp16 x
__device__ __align__(16) __half g_wh[3 * HID * ZW];        // fp16 W_gat
__device__ __align__(16) __half g_wf[INF * ZW];            // fp16 fused W_emb@W_gat0
__device__ float  g_bz[ZW];                                // fused bias row
__device__ __align__(16) __half g_zh[(size_t)NPAD * ZW];   // fp16 z
__device__ float  g_als[NPAD * HEADS];
__device__ float  g_ald[NPAD * HEADS];
__device__ int    g_deg[NNODES];
__device__ int    g_off[NNODES + 1];
__device__ int    g_cur[NNODES];
__device__ int    g_csr[ETOT];
__device__ int    g_bsum[256];
__device__ int    g_boff[256];
__device__ float  g_hg[NG * HID];

// ---------------- CSR build --------------------------------------------------
__global__ void k_count(const int* __restrict__ ei) {
    int e = blockIdx.x * blockDim.x + threadIdx.x;
    if (e >= NEDGES) return;
    atomicAdd(&g_deg[ei[NEDGES + e]], 1);
}

__global__ void k_bsum() {
    __shared__ int sm[256];
    int i = blockIdx.x * 256 + threadIdx.x;
    sm[threadIdx.x] = (i < NNODES) ? (g_deg[i] + 1) : 0;   // +1 self-loop
    __syncthreads();
    for (int o = 128; o; o >>= 1) {
        if (threadIdx.x < o) sm[threadIdx.x] += sm[threadIdx.x + o];
        __syncthreads();
    }
    if (threadIdx.x == 0) g_bsum[blockIdx.x] = sm[0];
}

__global__ void k_bscan() {
    __shared__ int sm[512];
    int t = threadIdx.x;
    sm[t] = 0;
    sm[256 + t] = (t < NBLK) ? g_bsum[t] : 0;
    __syncthreads();
    for (int d = 1; d < 256; d <<= 1) {
        int v = sm[256 + t - d];
        __syncthreads();
        sm[256 + t] += v;
        __syncthreads();
    }
    g_boff[t] = sm[255 + t];
    if (t == 0) g_off[NNODES] = ETOT;
}

__global__ void k_offsets() {
    __shared__ int sm[512];
    int t = threadIdx.x;
    int i = blockIdx.x * 256 + t;
    int d = (i < NNODES) ? (g_deg[i] + 1) : 0;
    sm[t] = 0;
    sm[256 + t] = d;
    __syncthreads();
    for (int dd = 1; dd < 256; dd <<= 1) {
        int v = sm[256 + t - dd];
        __syncthreads();
        sm[256 + t] += v;
        __syncthreads();
    }
    if (i < NNODES) {
        int run = g_boff[blockIdx.x] + sm[255 + t];
        g_off[i] = run;
        g_csr[run] = i;
        g_cur[i] = run + 1;
    }
}

__global__ void k_scatter(const int* __restrict__ ei) {
    int e = blockIdx.x * blockDim.x + threadIdx.x;
    if (e >= NEDGES) return;
    int s = ei[e];
    int p = atomicAdd(&g_cur[ei[NEDGES + e]], 1);
    g_csr[p] = s;
}

// ---------------- x fp32 -> fp16 (padded rows zeroed) -------------------------
__global__ void k_xcvt(const float* __restrict__ x) {
    int i = blockIdx.x * 256 + threadIdx.x;
    int n = i >> 4;
    int off = (i & 15) * 8;
    union { uint4 u; __half2 h[4]; } pk;
    if (n < NNODES) {
        float4 v0 = *(const float4*)&x[(size_t)n * INF + off];
        float4 v1 = *(const float4*)&x[(size_t)n * INF + off + 4];
        pk.h[0] = __floats2half2_rn(v0.x, v0.y);
        pk.h[1] = __floats2half2_rn(v0.z, v0.w);
        pk.h[2] = __floats2half2_rn(v1.x, v1.y);
        pk.h[3] = __floats2half2_rn(v1.z, v1.w);
    } else {
        pk.u = make_uint4(0, 0, 0, 0);
    }
    *(uint4*)&g_xh[(size_t)n * INF + off] = pk.u;
}

// ---------------- W_gat fp32 -> fp16 (all 3 layers) ---------------------------
__global__ void k_wcvt(const float* __restrict__ Wg) {
    int i = blockIdx.x * 256 + threadIdx.x;
    float4 v = ((const float4*)Wg)[i];
    __half2* dst = (__half2*)g_wh;
    dst[i * 2]     = __floats2half2_rn(v.x, v.y);
    dst[i * 2 + 1] = __floats2half2_rn(v.z, v.w);
}

// ---------------- fused weights: Wf = W_emb @ W_gat0, bz = b_emb @ W_gat0 -----
__global__ void k_wfuse(const float* __restrict__ Wemb,
                        const float* __restrict__ bemb,
                        const float* __restrict__ Wg0) {
    __shared__ float we[HID];
    int r = blockIdx.x;
    int c = threadIdx.x;
    if (r < INF) {
        if (c < HID) we[c] = Wemb[r * HID + c];
        __syncthreads();
        float acc = 0.f;
        #pragma unroll 8
        for (int k = 0; k < HID; k++) acc = fmaf(we[k], Wg0[k * ZW + c], acc);
        g_wf[r * ZW + c] = __float2half_rn(acc);
    } else {
        if (c < HID) we[c] = bemb[c];
        __syncthreads();
        float acc = 0.f;
        #pragma unroll 8
        for (int k = 0; k < HID; k++) acc = fmaf(we[k], Wg0[k * ZW + c], acc);
        g_bz[c] = acc;
    }
}

// ---------------- z GEMM via HMMA + fused logits ------------------------------
__global__ void __launch_bounds__(256, 2) k_z(int layer,
                                              const float* __restrict__ asrc,
                                              const float* __restrict__ adst) {
    __shared__ __align__(16) __half sA[64 * 72];
    __shared__ __align__(16) __half sB[64 * 264];
    const __half* A;
    const __half* B;
    int astride, kch;
    if (layer == 0) { A = g_xh; B = g_wf; astride = INF; kch = 2; }
    else { A = g_hh; B = g_wh + (size_t)layer * HID * ZW; astride = HID; kch = 1; }

    int tid = threadIdx.x;
    int lane = tid & 31, warp = tid >> 5;
    int wm = warp >> 2, wn = warp & 3;
    int n0 = blockIdx.x * 64;
    int rstride4 = astride >> 3;

    float acc[2][8][4];
    #pragma unroll
    for (int mt = 0; mt < 2; mt++)
        #pragma unroll
        for (int nt = 0; nt < 8; nt++)
            #pragma unroll
            for (int r = 0; r < 4; r++) acc[mt][nt][r] = 0.f;

    u32 sa = (u32)__cvta_generic_to_shared(sA);
    u32 sb = (u32)__cvta_generic_to_shared(sB);
    const uint4* a4 = (const uint4*)(A + (size_t)n0 * astride);
    const uint4* w4 = (const uint4*)B;

    for (int ch = 0; ch < kch; ch++) {
        if (ch) __syncthreads();
        #pragma unroll
        for (int j = 0; j < 2; j++) {
            int idx = tid + 256 * j;
            int row = idx >> 3, q = idx & 7;
            *(uint4*)&sA[row * 72 + q * 8] = a4[row * rstride4 + ch * 8 + q];
        }
        #pragma unroll
        for (int j = 0; j < 8; j++) {
            int idx = tid + 256 * j;
            int row = idx >> 5, q = idx & 31;
            *(uint4*)&sB[row * 264 + q * 8] = w4[(ch * 64 + row) * 32 + q];
        }
        __syncthreads();

        #pragma unroll
        for (int ks = 0; ks < 4; ks++) {
            u32 a[2][4];
            #pragma unroll
            for (int mt = 0; mt < 2; mt++) {
                u32 ad = sa + (u32)(((wm * 32 + mt * 16 + (lane & 15)) * 72
                                     + ks * 16 + (lane >> 4) * 8) << 1);
                LDSM4(a[mt][0], a[mt][1], a[mt][2], a[mt][3], ad);
            }
            #pragma unroll
            for (int nt2 = 0; nt2 < 4; nt2++) {
                u32 bd = sb + (u32)(((ks * 16 + (lane & 15)) * 264
                                     + wn * 64 + nt2 * 16 + (lane >> 4) * 8) << 1);
                u32 b0, b1, b2, b3;
                LDSM4T(b0, b1, b2, b3, bd);
                #pragma unroll
                for (int mt = 0; mt < 2; mt++) {
                    MMA16816(acc[mt][nt2 * 2],     a[mt][0], a[mt][1], a[mt][2], a[mt][3], b0, b1);
                    MMA16816(acc[mt][nt2 * 2 + 1], a[mt][0], a[mt][1], a[mt][2], a[mt][3], b2, b3);
                }
            }
        }
    }

    if (layer == 0) {
        #pragma unroll
        for (int nt = 0; nt < 8; nt++) {
            float2 b2 = ((const float2*)g_bz)[(wn * 64 + nt * 8) / 2 + (lane & 3)];
            #pragma unroll
            for (int mt = 0; mt < 2; mt++) {
                acc[mt][nt][0] += b2.x; acc[mt][nt][1] += b2.y;
                acc[mt][nt][2] += b2.x; acc[mt][nt][3] += b2.y;
            }
        }
    }

    float2 asv[8], adv[8];
    #pragma unroll
    for (int nt = 0; nt < 8; nt++) {
        int c = wn * 64 + nt * 8 + (lane & 3) * 2;
        asv[nt] = *(const float2*)&asrc[c];
        adv[nt] = *(const float2*)&adst[c];
    }
    #pragma unroll
    for (int mt = 0; mt < 2; mt++) {
        int r0 = n0 + wm * 32 + mt * 16 + (lane >> 2);
        float s0 = 0.f, s1 = 0.f, d0 = 0.f, d1 = 0.f;
        #pragma unroll
        for (int nt = 0; nt < 8; nt++) {
            s0 += acc[mt][nt][0] * asv[nt].x + acc[mt][nt][1] * asv[nt].y;
            s1 += acc[mt][nt][2] * asv[nt].x + acc[mt][nt][3] * asv[nt].y;
            d0 += acc[mt][nt][0] * adv[nt].x + acc[mt][nt][1] * adv[nt].y;
            d1 += acc[mt][nt][2] * adv[nt].x + acc[mt][nt][3] * adv[nt].y;
            int c = wn * 64 + nt * 8 + (lane & 3) * 2;
            *(__half2*)&g_zh[(size_t)r0 * ZW + c] =
                __floats2half2_rn(acc[mt][nt][0], acc[mt][nt][1]);
            *(__half2*)&g_zh[(size_t)(r0 + 8) * ZW + c] =
                __floats2half2_rn(acc[mt][nt][2], acc[mt][nt][3]);
        }
        #pragma unroll
        for (int o = 1; o <= 2; o <<= 1) {
            s0 += __shfl_xor_sync(0xffffffffu, s0, o);
            s1 += __shfl_xor_sync(0xffffffffu, s1, o);
            d0 += __shfl_xor_sync(0xffffffffu, d0, o);
            d1 += __shfl_xor_sync(0xffffffffu, d1, o);
        }
        if ((lane & 3) == 0) {
            g_als[r0 * HEADS + wn] = s0;
            g_als[(r0 + 8) * HEADS + wn] = s1;
            g_ald[r0 * HEADS + wn] = d0;
            g_ald[(r0 + 8) * HEADS + wn] = d1;
        }
    }
}

// ---------------- per-dst aggregation (warp/node, masked 8-wide bundles) ------
__global__ void __launch_bounds__(256) k_agg(const float* __restrict__ bg) {
    int wid = (blockIdx.x * blockDim.x + threadIdx.x) >> 5;
    if (wid >= NNODES) return;
    int n = wid;
    int lane = threadIdx.x & 31;
    int hh = lane >> 3;
    int fg = lane & 7;

    float ald = g_ald[n * HEADS + hh];
    float a0=0,a1=0,a2=0,a3=0,a4=0,a5=0,a6=0,a7=0;
    float dsum = 0.f;

    const uint4* zh4 = (const uint4*)g_zh;
    int zo = hh * 8 + fg;
    int beg = g_off[n], end = g_off[n + 1];
    for (int i = beg; i < end; i += 8) {
        int idx[8];
        #pragma unroll
        for (int k = 0; k < 8; k++) {
            int j = i + k;
            idx[k] = g_csr[j < end ? j : end - 1];
        }
        float lg[8];
        #pragma unroll
        for (int k = 0; k < 8; k++) lg[k] = g_als[idx[k] * HEADS + hh];
        uint4 v[8];
        #pragma unroll
        for (int k = 0; k < 8; k++) v[k] = zh4[(size_t)idx[k] * 32 + zo];
        float w[8];
        #pragma unroll
        for (int k = 0; k < 8; k++) {
            float e = lg[k] + ald;
            e = (e > 0.f) ? e : 0.2f * e;
            w[k] = (i + k < end) ? __expf(e) : 0.f;
            dsum += w[k];
        }
        #pragma unroll
        for (int k = 0; k < 8; k++) {
            const __half2* p = (const __half2*)&v[k];
            float2 q0 = __half22float2(p[0]), q1 = __half22float2(p[1]);
            float2 q2 = __half22float2(p[2]), q3 = __half22float2(p[3]);
            a0 = fmaf(w[k], q0.x, a0); a1 = fmaf(w[k], q0.y, a1);
            a2 = fmaf(w[k], q1.x, a2); a3 = fmaf(w[k], q1.y, a3);
            a4 = fmaf(w[k], q2.x, a4); a5 = fmaf(w[k], q2.y, a5);
            a6 = fmaf(w[k], q3.x, a6); a7 = fmaf(w[k], q3.y, a7);
        }
    }
    float inv = 1.f / (dsum + 1e-16f);
    a0*=inv; a1*=inv; a2*=inv; a3*=inv; a4*=inv; a5*=inv; a6*=inv; a7*=inv;

    #pragma unroll
    for (int m = 8; m <= 16; m <<= 1) {
        a0 += __shfl_xor_sync(0xffffffffu, a0, m);
        a1 += __shfl_xor_sync(0xffffffffu, a1, m);
        a2 += __shfl_xor_sync(0xffffffffu, a2, m);
        a3 += __shfl_xor_sync(0xffffffffu, a3, m);
        a4 += __shfl_xor_sync(0xffffffffu, a4, m);
        a5 += __shfl_xor_sync(0xffffffffu, a5, m);
        a6 += __shfl_xor_sync(0xffffffffu, a6, m);
        a7 += __shfl_xor_sync(0xffffffffu, a7, m);
    }
    if (hh == 0) {
        int fb = fg * 8;
        float r0 = fmaxf(0.25f * a0 + bg[fb + 0], 0.f);
        float r1 = fmaxf(0.25f * a1 + bg[fb + 1], 0.f);
        float r2 = fmaxf(0.25f * a2 + bg[fb + 2], 0.f);
        float r3 = fmaxf(0.25f * a3 + bg[fb + 3], 0.f);
        float r4 = fmaxf(0.25f * a4 + bg[fb + 4], 0.f);
        float r5 = fmaxf(0.25f * a5 + bg[fb + 5], 0.f);
        float r6 = fmaxf(0.25f * a6 + bg[fb + 6], 0.f);
        float r7 = fmaxf(0.25f * a7 + bg[fb + 7], 0.f);
        float* o = g_h + (size_t)n * HID + fb;
        ((float4*)o)[0] = make_float4(r0, r1, r2, r3);
        ((float4*)o)[1] = make_float4(r4, r5, r6, r7);
        union { uint4 u; __half2 h[4]; } pk;
        pk.h[0] = __floats2half2_rn(r0, r1);
        pk.h[1] = __floats2half2_rn(r2, r3);
        pk.h[2] = __floats2half2_rn(r4, r5);
        pk.h[3] = __floats2half2_rn(r6, r7);
        *(uint4*)&g_hh[(size_t)n * HID + fb] = pk.u;
    }
}

// ---------------- global mean pool --------------------------------------------
__global__ void k_pool(const int* __restrict__ batch) {
    __shared__ int s_lo, s_hi;
    __shared__ float red[256];
    int g = blockIdx.x;
    if (threadIdx.x == 0) {
        int lo = 0, hi = NNODES;
        while (lo < hi) { int m = (lo + hi) >> 1; if (batch[m] < g) lo = m + 1; else hi = m; }
        s_lo = lo;
        lo = 0; hi = NNODES;
        while (lo < hi) { int m = (lo + hi) >> 1; if (batch[m] < g + 1) lo = m + 1; else hi = m; }
        s_hi = lo;
    }
    __syncthreads();
    int lo = s_lo, hi = s_hi;
    int f = threadIdx.x & 63, r = threadIdx.x >> 6;
    float acc = 0.f;
    for (int n = lo + r; n < hi; n += 4) acc += g_h[(size_t)n * HID + f];
    red[threadIdx.x] = acc;
    __syncthreads();
    if (threadIdx.x < 64) {
        float v = red[f] + red[64 + f] + red[128 + f] + red[192 + f];
        float cnt = (float)max(hi - lo, 1);
        g_hg[g * HID + f] = v / cnt;
    }
}

// ---------------- final FC (2 outputs per thread) ------------------------------
__global__ void __launch_bounds__(256) k_fc(const float* __restrict__ Wfc,
                                            const float* __restrict__ bfc,
                                            float* __restrict__ out) {
    __shared__ float hg[NG * HID];
    int t = threadIdx.x;
    for (int i = t; i < NG * HID; i += 256) hg[i] = g_hg[i];
    __syncthreads();
    int o2 = blockIdx.x * 256 + t;
    if (o2 >= OUTF / 2) return;
    const float2* W2 = (const float2*)Wfc;
    float2 b2 = ((const float2*)bfc)[o2];
    float acc0[NG], acc1[NG];
    #pragma unroll
    for (int g = 0; g < NG; g++) { acc0[g] = b2.x; acc1[g] = b2.y; }
    for (int f = 0; f < HID; f++) {
        float2 w = W2[(size_t)f * (OUTF / 2) + o2];
        #pragma unroll
        for (int g = 0; g < NG; g++) {
            float hv = hg[g * HID + f];
            acc0[g] = fmaf(hv, w.x, acc0[g]);
            acc1[g] = fmaf(hv, w.y, acc1[g]);
        }
    }
    float2* out2 = (float2*)out;
    #pragma unroll
    for (int g = 0; g < NG; g++)
        out2[(size_t)g * (OUTF / 2) + o2] = make_float2(acc0[g], acc1[g]);
}

// ---------------- launch --------------------------------------------------------
extern "C" void kernel_launch(void* const* d_in, const int* in_sizes, int n_in,
                              void* d_out, int out_size) {
    const float* x     = (const float*)d_in[0];
    const int*   ei    = (const int*)d_in[1];
    const int*   batch = (const int*)d_in[3];
    const float* W_emb = (const float*)d_in[4];
    const float* b_emb = (const float*)d_in[5];
    const float* W_gat = (const float*)d_in[6];
    const float* a_src = (const float*)d_in[7];
    const float* a_dst = (const float*)d_in[8];
    const float* b_gat = (const float*)d_in[9];
    const float* W_fc  = (const float*)d_in[10];
    const float* b_fc  = (const float*)d_in[11];
    float* out = (float*)d_out;

    void* degp = nullptr;
    cudaGetSymbolAddress(&degp, g_deg);
    cudaMemsetAsync(degp, 0, NNODES * sizeof(int));

    // kernel launch #4 = k_z layer 0 (ncu capture window)
    k_xcvt<<<NPAD * 16 / 256, 256>>>(x);
    k_wcvt<<<48, 256>>>(W_gat);
    k_wfuse<<<INF + 1, 256>>>(W_emb, b_emb, W_gat);
    k_z<<<NZBLK, 256>>>(0, a_src, a_dst);
    k_count<<<(NEDGES + 255) / 256, 256>>>(ei);
    k_bsum<<<NBLK, 256>>>();
    k_bscan<<<1, 256>>>();
    k_offsets<<<NBLK, 256>>>();
    k_scatter<<<(NEDGES + 255) / 256, 256>>>(ei);
    k_agg<<<(NNODES * 32 + 255) / 256, 256>>>(b_gat);

    for (int l = 1; l < 3; l++) {
        k_z<<<NZBLK, 256>>>(l,
                            a_src + (size_t)l * HEADS * HID,
                            a_dst + (size_t)l * HEADS * HID);
        k_agg<<<(NNODES * 32 + 255) / 256, 256>>>(b_gat + (size_t)l * HID);
    }

    k_pool<<<NG, 256>>>(batch);
    k_fc<<<(OUTF / 2 + 255) / 256, 256>>>(W_fc, b_fc, out);
}

// round 16
// speedup vs baseline: 1.1822x; 1.1822x over previous
#include <cuda_runtime.h>
#include <cuda_bf16.h>
#include <cuda_fp16.h>
#include <cstdint>
#include <math.h>

typedef unsigned long long ull;
typedef unsigned int u32;

#define NNODES 50000
#define NEDGES 500000
#define ETOT   (NEDGES + NNODES)
#define INF    128
#define HID    64
#define HEADS  4
#define ZW     (HEADS * HID)       // 256
#define NG     16
#define OUTF   326000
#define NPAD   50048               // multiple of 128
#define NZBLK  (NPAD / 64)         // 782 z tiles
#define NBLK   196                 // ceil(NNODES/256)

#define LDSM4(r0,r1,r2,r3,addr) \
    asm volatile("ldmatrix.sync.aligned.m8n8.x4.shared.b16 {%0,%1,%2,%3}, [%4];" \
        : "=r"(r0),"=r"(r1),"=r"(r2),"=r"(r3) : "r"(addr))
#define LDSM4T(r0,r1,r2,r3,addr) \
    asm volatile("ldmatrix.sync.aligned.m8n8.x4.trans.shared.b16 {%0,%1,%2,%3}, [%4];" \
        : "=r"(r0),"=r"(r1),"=r"(r2),"=r"(r3) : "r"(addr))
#define MMA16816(d,a0,a1,a2,a3,b0,b1) \
    asm volatile("mma.sync.aligned.m16n8k16.row.col.f32.f16.f16.f32 " \
        "{%0,%1,%2,%3},{%4,%5,%6,%7},{%8,%9},{%0,%1,%2,%3};" \
        : "+f"(d[0]),"+f"(d[1]),"+f"(d[2]),"+f"(d[3]) \
        : "r"(a0),"r"(a1),"r"(a2),"r"(a3),"r"(b0),"r"(b1))

// ---------------- scratch ----------------------------------------------------
__device__ float  g_h[(size_t)NPAD * HID];                 // fp32 h (pool input)
__device__ __align__(16) __half g_hh[(size_t)NPAD * HID];  // fp16 h (GEMM input)
__device__ __align__(16) __half g_xh[(size_t)NPAD * INF];  // fp16 x
__device__ __align__(16) __half g_wh[3 * HID * ZW];        // fp16 W_gat
__device__ __align__(16) __half g_wf[INF * ZW];            // fp16 fused W_emb@W_gat0
__device__ float  g_bz[ZW];                                // fused bias row
__device__ __align__(16) __half g_zh[(size_t)NPAD * ZW];   // fp16 z
__device__ float  g_als[NPAD * HEADS];
__device__ float  g_ald[NPAD * HEADS];
__device__ int    g_deg[NNODES];
__device__ int    g_off[NNODES + 1];
__device__ int    g_cur[NNODES];
__device__ int    g_csr[ETOT];
__device__ int    g_bsum[256];
__device__ int    g_boff[256];
__device__ float  g_hg[NG * HID];

// ---------------- CSR build --------------------------------------------------
__global__ void k_count(const int* __restrict__ ei) {
    int e = blockIdx.x * blockDim.x + threadIdx.x;
    if (e >= NEDGES) return;
    atomicAdd(&g_deg[ei[NEDGES + e]], 1);
}

__global__ void k_bsum() {
    __shared__ int sm[256];
    int i = blockIdx.x * 256 + threadIdx.x;
    sm[threadIdx.x] = (i < NNODES) ? (g_deg[i] + 1) : 0;   // +1 self-loop
    __syncthreads();
    for (int o = 128; o; o >>= 1) {
        if (threadIdx.x < o) sm[threadIdx.x] += sm[threadIdx.x + o];
        __syncthreads();
    }
    if (threadIdx.x == 0) g_bsum[blockIdx.x] = sm[0];
}

__global__ void k_bscan() {
    __shared__ int sm[512];
    int t = threadIdx.x;
    sm[t] = 0;
    sm[256 + t] = (t < NBLK) ? g_bsum[t] : 0;
    __syncthreads();
    for (int d = 1; d < 256; d <<= 1) {
        int v = sm[256 + t - d];
        __syncthreads();
        sm[256 + t] += v;
        __syncthreads();
    }
    g_boff[t] = sm[255 + t];
    if (t == 0) g_off[NNODES] = ETOT;
}

__global__ void k_offsets() {
    __shared__ int sm[512];
    int t = threadIdx.x;
    int i = blockIdx.x * 256 + t;
    int d = (i < NNODES) ? (g_deg[i] + 1) : 0;
    sm[t] = 0;
    sm[256 + t] = d;
    __syncthreads();
    for (int dd = 1; dd < 256; dd <<= 1) {
        int v = sm[256 + t - dd];
        __syncthreads();
        sm[256 + t] += v;
        __syncthreads();
    }
    if (i < NNODES) {
        int run = g_boff[blockIdx.x] + sm[255 + t];
        g_off[i] = run;
        g_csr[run] = i;
        g_cur[i] = run + 1;
    }
}

__global__ void k_scatter(const int* __restrict__ ei) {
    int e = blockIdx.x * blockDim.x + threadIdx.x;
    if (e >= NEDGES) return;
    int s = ei[e];
    int p = atomicAdd(&g_cur[ei[NEDGES + e]], 1);
    g_csr[p] = s;
}

// ---------------- x fp32 -> fp16 (padded rows zeroed) -------------------------
__global__ void k_xcvt(const float* __restrict__ x) {
    int i = blockIdx.x * 256 + threadIdx.x;
    int n = i >> 4;
    int off = (i & 15) * 8;
    union { uint4 u; __half2 h[4]; } pk;
    if (n < NNODES) {
        float4 v0 = *(const float4*)&x[(size_t)n * INF + off];
        float4 v1 = *(const float4*)&x[(size_t)n * INF + off + 4];
        pk.h[0] = __floats2half2_rn(v0.x, v0.y);
        pk.h[1] = __floats2half2_rn(v0.z, v0.w);
        pk.h[2] = __floats2half2_rn(v1.x, v1.y);
        pk.h[3] = __floats2half2_rn(v1.z, v1.w);
    } else {
        pk.u = make_uint4(0, 0, 0, 0);
    }
    *(uint4*)&g_xh[(size_t)n * INF + off] = pk.u;
}

// ---------------- W_gat fp32 -> fp16 (all 3 layers) ---------------------------
__global__ void k_wcvt(const float* __restrict__ Wg) {
    int i = blockIdx.x * 256 + threadIdx.x;
    float4 v = ((const float4*)Wg)[i];
    __half2* dst = (__half2*)g_wh;
    dst[i * 2]     = __floats2half2_rn(v.x, v.y);
    dst[i * 2 + 1] = __floats2half2_rn(v.z, v.w);
}

// ---------------- fused weights: Wf = W_emb @ W_gat0, bz = b_emb @ W_gat0 -----
__global__ void k_wfuse(const float* __restrict__ Wemb,
                        const float* __restrict__ bemb,
                        const float* __restrict__ Wg0) {
    __shared__ float we[HID];
    int r = blockIdx.x;
    int c = threadIdx.x;
    if (r < INF) {
        if (c < HID) we[c] = Wemb[r * HID + c];
        __syncthreads();
        float acc = 0.f;
        #pragma unroll 8
        for (int k = 0; k < HID; k++) acc = fmaf(we[k], Wg0[k * ZW + c], acc);
        g_wf[r * ZW + c] = __float2half_rn(acc);
    } else {
        if (c < HID) we[c] = bemb[c];
        __syncthreads();
        float acc = 0.f;
        #pragma unroll 8
        for (int k = 0; k < HID; k++) acc = fmaf(we[k], Wg0[k * ZW + c], acc);
        g_bz[c] = acc;
    }
}

// ---------------- z GEMM via HMMA + fused logits ------------------------------
__global__ void __launch_bounds__(256, 2) k_z(int layer,
                                              const float* __restrict__ asrc,
                                              const float* __restrict__ adst) {
    __shared__ __align__(16) __half sA[64 * 72];
    __shared__ __align__(16) __half sB[64 * 264];
    const __half* A;
    const __half* B;
    int astride, kch;
    if (layer == 0) { A = g_xh; B = g_wf; astride = INF; kch = 2; }
    else { A = g_hh; B = g_wh + (size_t)layer * HID * ZW; astride = HID; kch = 1; }

    int tid = threadIdx.x;
    int lane = tid & 31, warp = tid >> 5;
    int wm = warp >> 2, wn = warp & 3;
    int n0 = blockIdx.x * 64;
    int rstride4 = astride >> 3;

    float acc[2][8][4];
    #pragma unroll
    for (int mt = 0; mt < 2; mt++)
        #pragma unroll
        for (int nt = 0; nt < 8; nt++)
            #pragma unroll
            for (int r = 0; r < 4; r++) acc[mt][nt][r] = 0.f;

    u32 sa = (u32)__cvta_generic_to_shared(sA);
    u32 sb = (u32)__cvta_generic_to_shared(sB);
    const uint4* a4 = (const uint4*)(A + (size_t)n0 * astride);
    const uint4* w4 = (const uint4*)B;

    for (int ch = 0; ch < kch; ch++) {
        if (ch) __syncthreads();
        #pragma unroll
        for (int j = 0; j < 2; j++) {
            int idx = tid + 256 * j;
            int row = idx >> 3, q = idx & 7;
            *(uint4*)&sA[row * 72 + q * 8] = a4[row * rstride4 + ch * 8 + q];
        }
        #pragma unroll
        for (int j = 0; j < 8; j++) {
            int idx = tid + 256 * j;
            int row = idx >> 5, q = idx & 31;
            *(uint4*)&sB[row * 264 + q * 8] = w4[(ch * 64 + row) * 32 + q];
        }
        __syncthreads();

        #pragma unroll
        for (int ks = 0; ks < 4; ks++) {
            u32 a[2][4];
            #pragma unroll
            for (int mt = 0; mt < 2; mt++) {
                u32 ad = sa + (u32)(((wm * 32 + mt * 16 + (lane & 15)) * 72
                                     + ks * 16 + (lane >> 4) * 8) << 1);
                LDSM4(a[mt][0], a[mt][1], a[mt][2], a[mt][3], ad);
            }
            #pragma unroll
            for (int nt2 = 0; nt2 < 4; nt2++) {
                u32 bd = sb + (u32)(((ks * 16 + (lane & 15)) * 264
                                     + wn * 64 + nt2 * 16 + (lane >> 4) * 8) << 1);
                u32 b0, b1, b2, b3;
                LDSM4T(b0, b1, b2, b3, bd);
                #pragma unroll
                for (int mt = 0; mt < 2; mt++) {
                    MMA16816(acc[mt][nt2 * 2],     a[mt][0], a[mt][1], a[mt][2], a[mt][3], b0, b1);
                    MMA16816(acc[mt][nt2 * 2 + 1], a[mt][0], a[mt][1], a[mt][2], a[mt][3], b2, b3);
                }
            }
        }
    }

    if (layer == 0) {
        #pragma unroll
        for (int nt = 0; nt < 8; nt++) {
            float2 b2 = ((const float2*)g_bz)[(wn * 64 + nt * 8) / 2 + (lane & 3)];
            #pragma unroll
            for (int mt = 0; mt < 2; mt++) {
                acc[mt][nt][0] += b2.x; acc[mt][nt][1] += b2.y;
                acc[mt][nt][2] += b2.x; acc[mt][nt][3] += b2.y;
            }
        }
    }

    float2 asv[8], adv[8];
    #pragma unroll
    for (int nt = 0; nt < 8; nt++) {
        int c = wn * 64 + nt * 8 + (lane & 3) * 2;
        asv[nt] = *(const float2*)&asrc[c];
        adv[nt] = *(const float2*)&adst[c];
    }
    #pragma unroll
    for (int mt = 0; mt < 2; mt++) {
        int r0 = n0 + wm * 32 + mt * 16 + (lane >> 2);
        float s0 = 0.f, s1 = 0.f, d0 = 0.f, d1 = 0.f;
        #pragma unroll
        for (int nt = 0; nt < 8; nt++) {
            s0 += acc[mt][nt][0] * asv[nt].x + acc[mt][nt][1] * asv[nt].y;
            s1 += acc[mt][nt][2] * asv[nt].x + acc[mt][nt][3] * asv[nt].y;
            d0 += acc[mt][nt][0] * adv[nt].x + acc[mt][nt][1] * adv[nt].y;
            d1 += acc[mt][nt][2] * adv[nt].x + acc[mt][nt][3] * adv[nt].y;
            int c = wn * 64 + nt * 8 + (lane & 3) * 2;
            *(__half2*)&g_zh[(size_t)r0 * ZW + c] =
                __floats2half2_rn(acc[mt][nt][0], acc[mt][nt][1]);
            *(__half2*)&g_zh[(size_t)(r0 + 8) * ZW + c] =
                __floats2half2_rn(acc[mt][nt][2], acc[mt][nt][3]);
        }
        #pragma unroll
        for (int o = 1; o <= 2; o <<= 1) {
            s0 += __shfl_xor_sync(0xffffffffu, s0, o);
            s1 += __shfl_xor_sync(0xffffffffu, s1, o);
            d0 += __shfl_xor_sync(0xffffffffu, d0, o);
            d1 += __shfl_xor_sync(0xffffffffu, d1, o);
        }
        if ((lane & 3) == 0) {
            g_als[r0 * HEADS + wn] = s0;
            g_als[(r0 + 8) * HEADS + wn] = s1;
            g_ald[r0 * HEADS + wn] = d0;
            g_ald[(r0 + 8) * HEADS + wn] = d1;
        }
    }
}

// ---------------- per-dst aggregation (warp/node, fp16 z, 4-way unroll) ------
__global__ void __launch_bounds__(256) k_agg(const float* __restrict__ bg) {
    int wid = (blockIdx.x * blockDim.x + threadIdx.x) >> 5;
    if (wid >= NNODES) return;
    int n = wid;
    int lane = threadIdx.x & 31;
    int hh = lane >> 3;
    int fg = lane & 7;

    float ald = g_ald[n * HEADS + hh];
    float a0=0,a1=0,a2=0,a3=0,a4=0,a5=0,a6=0,a7=0;
    float dsum = 0.f;

    const uint4* zh4 = (const uint4*)g_zh;
    int zo = hh * 8 + fg;
    int beg = g_off[n], end = g_off[n + 1];
    int i = beg;
    for (; i + 4 <= end; i += 4) {
        int s0 = g_csr[i], s1 = g_csr[i+1], s2 = g_csr[i+2], s3 = g_csr[i+3];
        float l0 = g_als[s0 * HEADS + hh];
        float l1 = g_als[s1 * HEADS + hh];
        float l2 = g_als[s2 * HEADS + hh];
        float l3 = g_als[s3 * HEADS + hh];
        uint4 v0 = zh4[(size_t)s0 * 32 + zo];
        uint4 v1 = zh4[(size_t)s1 * 32 + zo];
        uint4 v2 = zh4[(size_t)s2 * 32 + zo];
        uint4 v3 = zh4[(size_t)s3 * 32 + zo];
        float e0 = l0 + ald, e1 = l1 + ald, e2 = l2 + ald, e3 = l3 + ald;
        e0 = (e0 > 0.f) ? e0 : 0.2f * e0;
        e1 = (e1 > 0.f) ? e1 : 0.2f * e1;
        e2 = (e2 > 0.f) ? e2 : 0.2f * e2;
        e3 = (e3 > 0.f) ? e3 : 0.2f * e3;
        float w0 = __expf(e0), w1 = __expf(e1), w2 = __expf(e2), w3 = __expf(e3);
        dsum += (w0 + w1) + (w2 + w3);
        {
            const __half2* p = (const __half2*)&v0;
            float2 q0 = __half22float2(p[0]), q1 = __half22float2(p[1]);
            float2 q2 = __half22float2(p[2]), q3 = __half22float2(p[3]);
            a0 = fmaf(w0, q0.x, a0); a1 = fmaf(w0, q0.y, a1);
            a2 = fmaf(w0, q1.x, a2); a3 = fmaf(w0, q1.y, a3);
            a4 = fmaf(w0, q2.x, a4); a5 = fmaf(w0, q2.y, a5);
            a6 = fmaf(w0, q3.x, a6); a7 = fmaf(w0, q3.y, a7);
        }
        {
            const __half2* p = (const __half2*)&v1;
            float2 q0 = __half22float2(p[0]), q1 = __half22float2(p[1]);
            float2 q2 = __half22float2(p[2]), q3 = __half22float2(p[3]);
            a0 = fmaf(w1, q0.x, a0); a1 = fmaf(w1, q0.y, a1);
            a2 = fmaf(w1, q1.x, a2); a3 = fmaf(w1, q1.y, a3);
            a4 = fmaf(w1, q2.x, a4); a5 = fmaf(w1, q2.y, a5);
            a6 = fmaf(w1, q3.x, a6); a7 = fmaf(w1, q3.y, a7);
        }
        {
            const __half2* p = (const __half2*)&v2;
            float2 q0 = __half22float2(p[0]), q1 = __half22float2(p[1]);
            float2 q2 = __half22float2(p[2]), q3 = __half22float2(p[3]);
            a0 = fmaf(w2, q0.x, a0); a1 = fmaf(w2, q0.y, a1);
            a2 = fmaf(w2, q1.x, a2); a3 = fmaf(w2, q1.y, a3);
            a4 = fmaf(w2, q2.x, a4); a5 = fmaf(w2, q2.y, a5);
            a6 = fmaf(w2, q3.x, a6); a7 = fmaf(w2, q3.y, a7);
        }
        {
            const __half2* p = (const __half2*)&v3;
            float2 q0 = __half22float2(p[0]), q1 = __half22float2(p[1]);
            float2 q2 = __half22float2(p[2]), q3 = __half22float2(p[3]);
            a0 = fmaf(w3, q0.x, a0); a1 = fmaf(w3, q0.y, a1);
            a2 = fmaf(w3, q1.x, a2); a3 = fmaf(w3, q1.y, a3);
            a4 = fmaf(w3, q2.x, a4); a5 = fmaf(w3, q2.y, a5);
            a6 = fmaf(w3, q3.x, a6); a7 = fmaf(w3, q3.y, a7);
        }
    }
    for (; i < end; i++) {
        int s = g_csr[i];
        float e = g_als[s * HEADS + hh] + ald;
        e = (e > 0.f) ? e : 0.2f * e;
        float w = __expf(e);
        uint4 v = zh4[(size_t)s * 32 + zo];
        const __half2* p = (const __half2*)&v;
        float2 q0 = __half22float2(p[0]), q1 = __half22float2(p[1]);
        float2 q2 = __half22float2(p[2]), q3 = __half22float2(p[3]);
        dsum += w;
        a0 = fmaf(w, q0.x, a0); a1 = fmaf(w, q0.y, a1);
        a2 = fmaf(w, q1.x, a2); a3 = fmaf(w, q1.y, a3);
        a4 = fmaf(w, q2.x, a4); a5 = fmaf(w, q2.y, a5);
        a6 = fmaf(w, q3.x, a6); a7 = fmaf(w, q3.y, a7);
    }
    float inv = 1.f / (dsum + 1e-16f);
    a0*=inv; a1*=inv; a2*=inv; a3*=inv; a4*=inv; a5*=inv; a6*=inv; a7*=inv;

    #pragma unroll
    for (int m = 8; m <= 16; m <<= 1) {
        a0 += __shfl_xor_sync(0xffffffffu, a0, m);
        a1 += __shfl_xor_sync(0xffffffffu, a1, m);
        a2 += __shfl_xor_sync(0xffffffffu, a2, m);
        a3 += __shfl_xor_sync(0xffffffffu, a3, m);
        a4 += __shfl_xor_sync(0xffffffffu, a4, m);
        a5 += __shfl_xor_sync(0xffffffffu, a5, m);
        a6 += __shfl_xor_sync(0xffffffffu, a6, m);
        a7 += __shfl_xor_sync(0xffffffffu, a7, m);
    }
    if (hh == 0) {
        int fb = fg * 8;
        float r0 = fmaxf(0.25f * a0 + bg[fb + 0], 0.f);
        float r1 = fmaxf(0.25f * a1 + bg[fb + 1], 0.f);
        float r2 = fmaxf(0.25f * a2 + bg[fb + 2], 0.f);
        float r3 = fmaxf(0.25f * a3 + bg[fb + 3], 0.f);
        float r4 = fmaxf(0.25f * a4 + bg[fb + 4], 0.f);
        float r5 = fmaxf(0.25f * a5 + bg[fb + 5], 0.f);
        float r6 = fmaxf(0.25f * a6 + bg[fb + 6], 0.f);
        float r7 = fmaxf(0.25f * a7 + bg[fb + 7], 0.f);
        float* o = g_h + (size_t)n * HID + fb;
        ((float4*)o)[0] = make_float4(r0, r1, r2, r3);
        ((float4*)o)[1] = make_float4(r4, r5, r6, r7);
        union { uint4 u; __half2 h[4]; } pk;
        pk.h[0] = __floats2half2_rn(r0, r1);
        pk.h[1] = __floats2half2_rn(r2, r3);
        pk.h[2] = __floats2half2_rn(r4, r5);
        pk.h[3] = __floats2half2_rn(r6, r7);
        *(uint4*)&g_hh[(size_t)n * HID + fb] = pk.u;
    }
}

// ---------------- global mean pool --------------------------------------------
__global__ void k_pool(const int* __restrict__ batch) {
    __shared__ int s_lo, s_hi;
    __shared__ float red[256];
    int g = blockIdx.x;
    if (threadIdx.x == 0) {
        int lo = 0, hi = NNODES;
        while (lo < hi) { int m = (lo + hi) >> 1; if (batch[m] < g) lo = m + 1; else hi = m; }
        s_lo = lo;
        lo = 0; hi = NNODES;
        while (lo < hi) { int m = (lo + hi) >> 1; if (batch[m] < g + 1) lo = m + 1; else hi = m; }
        s_hi = lo;
    }
    __syncthreads();
    int lo = s_lo, hi = s_hi;
    int f = threadIdx.x & 63, r = threadIdx.x >> 6;
    float acc = 0.f;
    for (int n = lo + r; n < hi; n += 4) acc += g_h[(size_t)n * HID + f];
    red[threadIdx.x] = acc;
    __syncthreads();
    if (threadIdx.x < 64) {
        float v = red[f] + red[64 + f] + red[128 + f] + red[192 + f];
        float cnt = (float)max(hi - lo, 1);
        g_hg[g * HID + f] = v / cnt;
    }
}

// ---------------- final FC (2 outputs per thread) ------------------------------
__global__ void __launch_bounds__(256) k_fc(const float* __restrict__ Wfc,
                                            const float* __restrict__ bfc,
                                            float* __restrict__ out) {
    __shared__ float hg[NG * HID];
    int t = threadIdx.x;
    for (int i = t; i < NG * HID; i += 256) hg[i] = g_hg[i];
    __syncthreads();
    int o2 = blockIdx.x * 256 + t;
    if (o2 >= OUTF / 2) return;
    const float2* W2 = (const float2*)Wfc;
    float2 b2 = ((const float2*)bfc)[o2];
    float acc0[NG], acc1[NG];
    #pragma unroll
    for (int g = 0; g < NG; g++) { acc0[g] = b2.x; acc1[g] = b2.y; }
    for (int f = 0; f < HID; f++) {
        float2 w = W2[(size_t)f * (OUTF / 2) + o2];
        #pragma unroll
        for (int g = 0; g < NG; g++) {
            float hv = hg[g * HID + f];
            acc0[g] = fmaf(hv, w.x, acc0[g]);
            acc1[g] = fmaf(hv, w.y, acc1[g]);
        }
    }
    float2* out2 = (float2*)out;
    #pragma unroll
    for (int g = 0; g < NG; g++)
        out2[(size_t)g * (OUTF / 2) + o2] = make_float2(acc0[g], acc1[g]);
}

// ---------------- launch --------------------------------------------------------
extern "C" void kernel_launch(void* const* d_in, const int* in_sizes, int n_in,
                              void* d_out, int out_size) {
    const float* x     = (const float*)d_in[0];
    const int*   ei    = (const int*)d_in[1];
    const int*   batch = (const int*)d_in[3];
    const float* W_emb = (const float*)d_in[4];
    const float* b_emb = (const float*)d_in[5];
    const float* W_gat = (const float*)d_in[6];
    const float* a_src = (const float*)d_in[7];
    const float* a_dst = (const float*)d_in[8];
    const float* b_gat = (const float*)d_in[9];
    const float* W_fc  = (const float*)d_in[10];
    const float* b_fc  = (const float*)d_in[11];
    float* out = (float*)d_out;

    void* degp = nullptr;
    cudaGetSymbolAddress(&degp, g_deg);

    // Fork a side stream for the CSR build, overlapping it with the GEMM chain.
    cudaStream_t s2 = 0;
    cudaEvent_t ev1 = 0, ev2 = 0;
    bool fork = (cudaStreamCreateWithFlags(&s2, cudaStreamNonBlocking) == cudaSuccess);
    if (fork) fork = (cudaEventCreateWithFlags(&ev1, cudaEventDisableTiming) == cudaSuccess);
    if (fork) fork = (cudaEventCreateWithFlags(&ev2, cudaEventDisableTiming) == cudaSuccess);

    cudaMemsetAsync(degp, 0, NNODES * sizeof(int));

    if (fork) {
        cudaEventRecord(ev1, 0);
        cudaStreamWaitEvent(s2, ev1, 0);
        k_count<<<(NEDGES + 255) / 256, 256, 0, s2>>>(ei);
        k_bsum<<<NBLK, 256, 0, s2>>>();
        k_bscan<<<1, 256, 0, s2>>>();
        k_offsets<<<NBLK, 256, 0, s2>>>();
        k_scatter<<<(NEDGES + 255) / 256, 256, 0, s2>>>(ei);
        cudaEventRecord(ev2, s2);
    } else {
        k_count<<<(NEDGES + 255) / 256, 256>>>(ei);
        k_bsum<<<NBLK, 256>>>();
        k_bscan<<<1, 256>>>();
        k_offsets<<<NBLK, 256>>>();
        k_scatter<<<(NEDGES + 255) / 256, 256>>>(ei);
    }

    // main stream: GEMM prep + z0 (overlaps with CSR build)
    k_xcvt<<<NPAD * 16 / 256, 256>>>(x);
    k_wcvt<<<48, 256>>>(W_gat);
    k_wfuse<<<INF + 1, 256>>>(W_emb, b_emb, W_gat);
    k_z<<<NZBLK, 256>>>(0, a_src, a_dst);

    if (fork) cudaStreamWaitEvent(0, ev2, 0);   // join: agg needs CSR
    k_agg<<<(NNODES * 32 + 255) / 256, 256>>>(b_gat);

    for (int l = 1; l < 3; l++) {
        k_z<<<NZBLK, 256>>>(l,
                            a_src + (size_t)l * HEADS * HID,
                            a_dst + (size_t)l * HEADS * HID);
        k_agg<<<(NNODES * 32 + 255) / 256, 256>>>(b_gat + (size_t)l * HID);
    }

    k_pool<<<NG, 256>>>(batch);
    k_fc<<<(OUTF / 2 + 255) / 256, 256>>>(W_fc, b_fc, out);
}